// round 2
// baseline (speedup 1.0000x reference)
#include <cuda_runtime.h>
#include <cuda_fp16.h>
#include <math.h>
#include <stdint.h>

// Problem constants
#define BQ   32      // batch
#define CINC 64      // input channels
#define HH   32      // height
#define WW   128     // width
#define OCC  128     // output channels
#define G5   640     // 5*OC gate width
#define KKK  320     // GEMM K = 128 (h_up) + 128 (h_lf) + 64 (x)
#define NDIR 4

#define MTILE 128    // GEMM M tile (4 cells x 32 batch)
#define NTILE 160    // GEMM N tile (5 gates x 32 channels, permuted)
#define AKH   328    // padded K stride (halves) for smem tiles
#define CPAD  164    // padded stride (floats) for C smem

#define SMEM_BYTES ((MTILE + NTILE) * AKH * 2)   // 188,928 B

// -------- device scratch (static allocation; no cudaMalloc allowed) --------
__device__ __half d_xT16[HH][WW][BQ][CINC];          // 16 MB, x transposed fp16
__device__ __half d_BpT[NDIR][G5][KKK];              // 1.6 MB, permuted weights, N-major
__device__ float  d_biasP[NDIR][G5];                 // permuted bias (fp32)
__device__ __half d_h16[NDIR][HH][WW][BQ][OCC];      // 128 MB, h state fp16 (GEMM operand)
__device__ float  d_h32[NDIR][HH][WW][BQ][OCC];      // 256 MB, h state fp32 (output source)
__device__ float  d_c32[NDIR][HH][WW][BQ][OCC];      // 256 MB, c state fp32

// ---------------------------------------------------------------------------
// prep kernels
// ---------------------------------------------------------------------------
__global__ void prep_x(const float* __restrict__ x) {
    int i = blockIdx.x * blockDim.x + threadIdx.x;
    if (i >= HH * WW * BQ * CINC) return;
    int cin = i & 63;
    int b   = (i >> 6) & 31;
    int xw  = (i >> 11) & 127;
    int y   = i >> 18;
    ((__half*)d_xT16)[i] = __float2half(x[((b * CINC + cin) * HH + y) * WW + xw]);
}

__global__ void prep_w(const float* __restrict__ w0,
                       const float* __restrict__ u0,
                       const float* __restrict__ u1) {
    int i = blockIdx.x * blockDim.x + threadIdx.x;
    if (i >= NDIR * G5 * KKK) return;
    int k    = i % KKK;
    int pcol = (i / KKK) % G5;
    int d    = i / (G5 * KKK);
    int cbl  = pcol / NTILE;
    int rem  = pcol % NTILE;
    int gate = rem / 32;
    int lane = rem % 32;
    int gcol = gate * 128 + cbl * 32 + lane;   // original gate column
    float v;
    if (k < 128)        v = u0[(d * 128 + k) * G5 + gcol];
    else if (k < 256)   v = u1[(d * 128 + (k - 128)) * G5 + gcol];
    else                v = w0[(d * 64  + (k - 256)) * G5 + gcol];
    ((__half*)d_BpT)[i] = __float2half(v);
}

__global__ void prep_b(const float* __restrict__ bias) {
    int i = blockIdx.x * blockDim.x + threadIdx.x;
    if (i >= NDIR * G5) return;
    int pcol = i % G5;
    int d    = i / G5;
    int cbl  = pcol / NTILE;
    int rem  = pcol % NTILE;
    int gate = rem / 32;
    int lane = rem % 32;
    int gcol = gate * 128 + cbl * 32 + lane;
    d_biasP[d][pcol] = bias[d * G5 + gcol];
}

// ---------------------------------------------------------------------------
// one anti-diagonal wavefront: GEMM (fp16 HMMA, fp32 accum) + LSTM epilogue
// grid: (ceil(len/4), 4 channel-blocks, 4 directions), block: 256 threads
// ---------------------------------------------------------------------------
__device__ __forceinline__ float sigmoidf_(float v) {
    return 1.0f / (1.0f + expf(-v));
}

__global__ void __launch_bounds__(256, 1) diag_kernel(int t) {
    int y0 = t - (WW - 1); if (y0 < 0) y0 = 0;
    int y1 = (t < HH - 1) ? t : (HH - 1);
    const int len   = y1 - y0 + 1;
    const int mtile = blockIdx.x;
    const int cb    = blockIdx.y;
    const int d     = blockIdx.z;

    extern __shared__ __align__(16) char smem_raw[];
    __half* As  = (__half*)smem_raw;              // [128][AKH] halves
    __half* Bs  = As + MTILE * AKH;               // [160][AKH] halves (N-major)
    float*  Csm = (float*)smem_raw;               // [128][CPAD] floats, reuses As

    const int tid = threadIdx.x;

    // ---- stage A tile: rows = (cell, batch), cols = [h_up | h_lf | x] ----
    for (int c = tid; c < MTILE * 40; c += 256) {
        int r  = c / 40;
        int q  = c - r * 40;         // which uint4 (8 halves) of the 320-half row
        int cl = r >> 5, b = r & 31;
        int cell = mtile * 4 + cl;
        uint4 v = make_uint4(0u, 0u, 0u, 0u);
        if (cell < len) {
            int y  = y0 + cell;
            int xw = t - y;
            int k  = q * 8;
            if (k < 128) {
                if (y > 0) v = *(const uint4*)&d_h16[d][y - 1][xw][b][k];
            } else if (k < 256) {
                if (xw > 0) v = *(const uint4*)&d_h16[d][y][xw - 1][b][k - 128];
            } else {
                int fy = (d & 2) ? (HH - 1 - y)  : y;
                int fx = (d & 1) ? (WW - 1 - xw) : xw;
                v = *(const uint4*)&d_xT16[fy][fx][b][k - 256];
            }
        }
        *(uint4*)&As[r * AKH + q * 8] = v;
    }
    // ---- stage B slice (already permuted + N-major in global) ----
    for (int c = tid; c < NTILE * 40; c += 256) {
        int n = c / 40;
        int q = c - n * 40;
        *(uint4*)&Bs[n * AKH + q * 8] =
            *(const uint4*)&d_BpT[d][cb * NTILE + n][q * 8];
    }
    __syncthreads();

    // ---- MMA mainloop: 8 warps = 4 (M) x 2 (N); warp tile 32 x 80 ----
    const int warp = tid >> 5;
    const int lane = tid & 31;
    const int wm = warp & 3;      // row block: wm*32
    const int wn = warp >> 2;     // col block: wn*80
    const int g  = lane >> 2;
    const int tq = lane & 3;

    float acc[2][10][4];
#pragma unroll
    for (int mi = 0; mi < 2; mi++)
#pragma unroll
        for (int ni = 0; ni < 10; ni++)
#pragma unroll
            for (int e = 0; e < 4; e++) acc[mi][ni][e] = 0.0f;

    const __half* Abase = &As[(wm * 32 + g) * AKH + tq * 2];
    const __half* Bbase = &Bs[(wn * 80 + g) * AKH + tq * 2];

#pragma unroll 2
    for (int ks = 0; ks < 20; ks++) {
        const int k0 = ks * 16;
        uint32_t afr[2][4];
#pragma unroll
        for (int mi = 0; mi < 2; mi++) {
            const __half* p = Abase + mi * 16 * AKH + k0;
            afr[mi][0] = *(const uint32_t*)(p);
            afr[mi][1] = *(const uint32_t*)(p + 8 * AKH);
            afr[mi][2] = *(const uint32_t*)(p + 8);
            afr[mi][3] = *(const uint32_t*)(p + 8 * AKH + 8);
        }
#pragma unroll
        for (int ni = 0; ni < 10; ni++) {
            const __half* p = Bbase + ni * 8 * AKH + k0;
            uint32_t b0 = *(const uint32_t*)(p);
            uint32_t b1 = *(const uint32_t*)(p + 8);
#pragma unroll
            for (int mi = 0; mi < 2; mi++) {
                asm volatile(
                    "mma.sync.aligned.m16n8k16.row.col.f32.f16.f16.f32 "
                    "{%0,%1,%2,%3}, {%4,%5,%6,%7}, {%8,%9}, {%0,%1,%2,%3};\n"
                    : "+f"(acc[mi][ni][0]), "+f"(acc[mi][ni][1]),
                      "+f"(acc[mi][ni][2]), "+f"(acc[mi][ni][3])
                    : "r"(afr[mi][0]), "r"(afr[mi][1]),
                      "r"(afr[mi][2]), "r"(afr[mi][3]),
                      "r"(b0), "r"(b1));
            }
        }
    }
    __syncthreads();   // all warps done reading As before overwriting with Csm

    // ---- spill C to smem so the epilogue sees all 5 gates per channel ----
#pragma unroll
    for (int mi = 0; mi < 2; mi++) {
#pragma unroll
        for (int ni = 0; ni < 10; ni++) {
            int row = wm * 32 + mi * 16 + g;
            int col = wn * 80 + ni * 8 + tq * 2;
            *(float2*)&Csm[row * CPAD + col] =
                make_float2(acc[mi][ni][0], acc[mi][ni][1]);
            *(float2*)&Csm[(row + 8) * CPAD + col] =
                make_float2(acc[mi][ni][2], acc[mi][ni][3]);
        }
    }
    __syncthreads();

    // ---- LSTM epilogue (fp32): 128 rows x 32 channels ----
    for (int it = tid; it < MTILE * 32; it += 256) {
        int r = it >> 5;
        int j = it & 31;
        int cl = r >> 5, b = r & 31;
        int cell = mtile * 4 + cl;
        if (cell >= len) continue;
        int y  = y0 + cell;
        int xw = t - y;
        const float* cr = &Csm[r * CPAD];
        const float* bp = &d_biasP[d][cb * NTILE];
        float gi = cr[j]       + bp[j];
        float gf = cr[32 + j]  + bp[32 + j];
        float gg = cr[64 + j]  + bp[64 + j];
        float go = cr[96 + j]  + bp[96 + j];
        float gl = cr[128 + j] + bp[128 + j];
        float iv = sigmoidf_(gi);
        float fv = sigmoidf_(gf);
        float gv = tanhf(gg);
        float ov = sigmoidf_(go);
        float lv = sigmoidf_(gl);
        int oc = cb * 32 + j;
        float cup = (y  > 0) ? d_c32[d][y - 1][xw][b][oc] : 0.0f;
        float clf = (xw > 0) ? d_c32[d][y][xw - 1][b][oc] : 0.0f;
        float cn = fv * (lv * cup + (1.0f - lv) * clf) + iv * gv;
        float hn = ov * tanhf(cn);
        d_c32[d][y][xw][b][oc] = cn;
        d_h32[d][y][xw][b][oc] = hn;
        d_h16[d][y][xw][b][oc] = __float2half(hn);
    }
}

// ---------------------------------------------------------------------------
// final transpose: h32[d][y][xw][b][oc] -> out[b][d][oc][y][xw]
// block per (d, y, b, oc-chunk), smem 128x32 tile
// ---------------------------------------------------------------------------
__global__ void __launch_bounds__(256) finalize_kernel(float* __restrict__ out) {
    int bid = blockIdx.x;
    int occ = bid & 3;
    int b   = (bid >> 2) & 31;
    int y   = (bid >> 7) & 31;
    int d   = bid >> 12;

    __shared__ float sm[128][33];

    for (int i = threadIdx.x; i < 128 * 32; i += 256) {
        int xw = i >> 5;
        int j  = i & 31;
        sm[xw][j] = d_h32[d][y][xw][b][occ * 32 + j];
    }
    __syncthreads();
    for (int i = threadIdx.x; i < 32 * 128; i += 256) {
        int j  = i >> 7;        // channel lane
        int xw = i & 127;       // contiguous writes
        int oc = occ * 32 + j;
        out[(((size_t)(b * 4 + d) * OCC + oc) * HH + y) * WW + xw] = sm[xw][j];
    }
}

// ---------------------------------------------------------------------------
// launch
// ---------------------------------------------------------------------------
extern "C" void kernel_launch(void* const* d_in, const int* in_sizes, int n_in,
                              void* d_out, int out_size) {
    const float* x  = (const float*)d_in[0];
    const float* w0 = (const float*)d_in[1];
    const float* u0 = (const float*)d_in[2];
    const float* u1 = (const float*)d_in[3];
    const float* bb = (const float*)d_in[4];
    float* out = (float*)d_out;
    (void)in_sizes; (void)n_in; (void)out_size;

    cudaFuncSetAttribute(diag_kernel,
                         cudaFuncAttributeMaxDynamicSharedMemorySize, SMEM_BYTES);

    prep_x<<<(HH * WW * BQ * CINC + 255) / 256, 256>>>(x);
    prep_w<<<(NDIR * G5 * KKK + 255) / 256, 256>>>(w0, u0, u1);
    prep_b<<<(NDIR * G5 + 255) / 256, 256>>>(bb);

    for (int t = 0; t < HH + WW - 1; t++) {
        int y0 = t - (WW - 1); if (y0 < 0) y0 = 0;
        int y1 = (t < HH - 1) ? t : (HH - 1);
        int len = y1 - y0 + 1;
        dim3 grid((len + 3) / 4, 4, NDIR);
        diag_kernel<<<grid, 256, SMEM_BYTES>>>(t);
    }

    finalize_kernel<<<NDIR * HH * BQ * 4, 256>>>(out);
}

// round 3
// speedup vs baseline: 1.0007x; 1.0007x over previous
#include <cuda_runtime.h>
#include <cuda_fp16.h>
#include <math.h>
#include <stdint.h>

// Problem constants
#define BQ   32      // batch
#define CINC 64      // input channels
#define HH   32      // height
#define WW   128     // width
#define OCC  128     // output channels
#define G5   640     // 5*OC gate width
#define KKK  320     // GEMM K = 128 (h_up) + 128 (h_lf) + 64 (x)
#define NDIR 4

#define MTILE 128    // GEMM M tile (4 cells x 32 batch)
#define NTILE 160    // GEMM N tile (5 gates x 32 channels, permuted)
#define AKH   328    // padded K stride (halves) for smem tiles
#define CPAD  164    // padded stride (floats) for C smem

#define SMEM_BYTES ((MTILE + NTILE) * AKH * 2)   // 188,928 B

// -------- device scratch (static allocation; no cudaMalloc allowed) --------
__device__ __half d_xT16[HH][WW][BQ][CINC];          // 16 MB, x transposed fp16
__device__ __half d_BpT[NDIR][G5][KKK];              // 1.6 MB, permuted weights, N-major
__device__ float  d_biasP[NDIR][G5];                 // permuted bias (fp32)
__device__ __half d_h16[NDIR][HH][WW][BQ][OCC];      // 128 MB, h state fp16 (GEMM operand)
__device__ float  d_h32[NDIR][HH][WW][BQ][OCC];      // 256 MB, h state fp32 (output source)
__device__ float  d_c32[NDIR][HH][WW][BQ][OCC];      // 256 MB, c state fp32

// ---------------------------------------------------------------------------
// prep kernels
// ---------------------------------------------------------------------------
__global__ void prep_x(const float* __restrict__ x) {
    int i = blockIdx.x * blockDim.x + threadIdx.x;
    if (i >= HH * WW * BQ * CINC) return;
    int cin = i & 63;
    int b   = (i >> 6) & 31;
    int xw  = (i >> 11) & 127;
    int y   = i >> 18;
    ((__half*)d_xT16)[i] = __float2half(x[((b * CINC + cin) * HH + y) * WW + xw]);
}

__global__ void prep_w(const float* __restrict__ w0,
                       const float* __restrict__ u0,
                       const float* __restrict__ u1) {
    int i = blockIdx.x * blockDim.x + threadIdx.x;
    if (i >= NDIR * G5 * KKK) return;
    int k    = i % KKK;
    int pcol = (i / KKK) % G5;
    int d    = i / (G5 * KKK);
    int cbl  = pcol / NTILE;
    int rem  = pcol % NTILE;
    int gate = rem / 32;
    int lane = rem % 32;
    int gcol = gate * 128 + cbl * 32 + lane;   // original gate column
    float v;
    if (k < 128)        v = u0[(d * 128 + k) * G5 + gcol];
    else if (k < 256)   v = u1[(d * 128 + (k - 128)) * G5 + gcol];
    else                v = w0[(d * 64  + (k - 256)) * G5 + gcol];
    ((__half*)d_BpT)[i] = __float2half(v);
}

__global__ void prep_b(const float* __restrict__ bias) {
    int i = blockIdx.x * blockDim.x + threadIdx.x;
    if (i >= NDIR * G5) return;
    int pcol = i % G5;
    int d    = i / G5;
    int cbl  = pcol / NTILE;
    int rem  = pcol % NTILE;
    int gate = rem / 32;
    int lane = rem % 32;
    int gcol = gate * 128 + cbl * 32 + lane;
    d_biasP[d][pcol] = bias[d * G5 + gcol];
}

// ---------------------------------------------------------------------------
// one anti-diagonal wavefront: GEMM (fp16 HMMA, fp32 accum) + LSTM epilogue
// grid: (ceil(len/4), 4 channel-blocks, 4 directions), block: 256 threads
// ---------------------------------------------------------------------------
__device__ __forceinline__ float sigmoidf_(float v) {
    return 1.0f / (1.0f + expf(-v));
}

__global__ void __launch_bounds__(256, 1) diag_kernel(int t) {
    int y0 = t - (WW - 1); if (y0 < 0) y0 = 0;
    int y1 = (t < HH - 1) ? t : (HH - 1);
    const int len   = y1 - y0 + 1;
    const int mtile = blockIdx.x;
    const int cb    = blockIdx.y;
    const int d     = blockIdx.z;

    extern __shared__ __align__(16) char smem_raw[];
    __half* As  = (__half*)smem_raw;              // [128][AKH] halves
    __half* Bs  = As + MTILE * AKH;               // [160][AKH] halves (N-major)
    float*  Csm = (float*)smem_raw;               // [128][CPAD] floats, reuses As

    const int tid = threadIdx.x;

    // ---- stage A tile: rows = (cell, batch), cols = [h_up | h_lf | x] ----
    for (int c = tid; c < MTILE * 40; c += 256) {
        int r  = c / 40;
        int q  = c - r * 40;         // which uint4 (8 halves) of the 320-half row
        int cl = r >> 5, b = r & 31;
        int cell = mtile * 4 + cl;
        uint4 v = make_uint4(0u, 0u, 0u, 0u);
        if (cell < len) {
            int y  = y0 + cell;
            int xw = t - y;
            int k  = q * 8;
            if (k < 128) {
                if (y > 0) v = *(const uint4*)&d_h16[d][y - 1][xw][b][k];
            } else if (k < 256) {
                if (xw > 0) v = *(const uint4*)&d_h16[d][y][xw - 1][b][k - 128];
            } else {
                int fy = (d & 2) ? (HH - 1 - y)  : y;
                int fx = (d & 1) ? (WW - 1 - xw) : xw;
                v = *(const uint4*)&d_xT16[fy][fx][b][k - 256];
            }
        }
        *(uint4*)&As[r * AKH + q * 8] = v;
    }
    // ---- stage B slice (already permuted + N-major in global) ----
    for (int c = tid; c < NTILE * 40; c += 256) {
        int n = c / 40;
        int q = c - n * 40;
        *(uint4*)&Bs[n * AKH + q * 8] =
            *(const uint4*)&d_BpT[d][cb * NTILE + n][q * 8];
    }
    __syncthreads();

    // ---- MMA mainloop: 8 warps = 4 (M) x 2 (N); warp tile 32 x 80 ----
    const int warp = tid >> 5;
    const int lane = tid & 31;
    const int wm = warp & 3;      // row block: wm*32
    const int wn = warp >> 2;     // col block: wn*80
    const int g  = lane >> 2;
    const int tq = lane & 3;

    float acc[2][10][4];
#pragma unroll
    for (int mi = 0; mi < 2; mi++)
#pragma unroll
        for (int ni = 0; ni < 10; ni++)
#pragma unroll
            for (int e = 0; e < 4; e++) acc[mi][ni][e] = 0.0f;

    const __half* Abase = &As[(wm * 32 + g) * AKH + tq * 2];
    const __half* Bbase = &Bs[(wn * 80 + g) * AKH + tq * 2];

#pragma unroll 2
    for (int ks = 0; ks < 20; ks++) {
        const int k0 = ks * 16;
        uint32_t afr[2][4];
#pragma unroll
        for (int mi = 0; mi < 2; mi++) {
            const __half* p = Abase + mi * 16 * AKH + k0;
            afr[mi][0] = *(const uint32_t*)(p);
            afr[mi][1] = *(const uint32_t*)(p + 8 * AKH);
            afr[mi][2] = *(const uint32_t*)(p + 8);
            afr[mi][3] = *(const uint32_t*)(p + 8 * AKH + 8);
        }
#pragma unroll
        for (int ni = 0; ni < 10; ni++) {
            const __half* p = Bbase + ni * 8 * AKH + k0;
            uint32_t b0 = *(const uint32_t*)(p);
            uint32_t b1 = *(const uint32_t*)(p + 8);
#pragma unroll
            for (int mi = 0; mi < 2; mi++) {
                asm volatile(
                    "mma.sync.aligned.m16n8k16.row.col.f32.f16.f16.f32 "
                    "{%0,%1,%2,%3}, {%4,%5,%6,%7}, {%8,%9}, {%0,%1,%2,%3};\n"
                    : "+f"(acc[mi][ni][0]), "+f"(acc[mi][ni][1]),
                      "+f"(acc[mi][ni][2]), "+f"(acc[mi][ni][3])
                    : "r"(afr[mi][0]), "r"(afr[mi][1]),
                      "r"(afr[mi][2]), "r"(afr[mi][3]),
                      "r"(b0), "r"(b1));
            }
        }
    }
    __syncthreads();   // all warps done reading As before overwriting with Csm

    // ---- spill C to smem so the epilogue sees all 5 gates per channel ----
#pragma unroll
    for (int mi = 0; mi < 2; mi++) {
#pragma unroll
        for (int ni = 0; ni < 10; ni++) {
            int row = wm * 32 + mi * 16 + g;
            int col = wn * 80 + ni * 8 + tq * 2;
            *(float2*)&Csm[row * CPAD + col] =
                make_float2(acc[mi][ni][0], acc[mi][ni][1]);
            *(float2*)&Csm[(row + 8) * CPAD + col] =
                make_float2(acc[mi][ni][2], acc[mi][ni][3]);
        }
    }
    __syncthreads();

    // ---- LSTM epilogue (fp32): 128 rows x 32 channels ----
    for (int it = tid; it < MTILE * 32; it += 256) {
        int r = it >> 5;
        int j = it & 31;
        int cl = r >> 5, b = r & 31;
        int cell = mtile * 4 + cl;
        if (cell >= len) continue;
        int y  = y0 + cell;
        int xw = t - y;
        const float* cr = &Csm[r * CPAD];
        const float* bp = &d_biasP[d][cb * NTILE];
        float gi = cr[j]       + bp[j];
        float gf = cr[32 + j]  + bp[32 + j];
        float gg = cr[64 + j]  + bp[64 + j];
        float go = cr[96 + j]  + bp[96 + j];
        float gl = cr[128 + j] + bp[128 + j];
        float iv = sigmoidf_(gi);
        float fv = sigmoidf_(gf);
        float gv = tanhf(gg);
        float ov = sigmoidf_(go);
        float lv = sigmoidf_(gl);
        int oc = cb * 32 + j;
        float cup = (y  > 0) ? d_c32[d][y - 1][xw][b][oc] : 0.0f;
        float clf = (xw > 0) ? d_c32[d][y][xw - 1][b][oc] : 0.0f;
        float cn = fv * (lv * cup + (1.0f - lv) * clf) + iv * gv;
        float hn = ov * tanhf(cn);
        d_c32[d][y][xw][b][oc] = cn;
        d_h32[d][y][xw][b][oc] = hn;
        d_h16[d][y][xw][b][oc] = __float2half(hn);
    }
}

// ---------------------------------------------------------------------------
// final transpose: h32[d][y][xw][b][oc] -> out[b][d][oc][y][xw]
// block per (d, y, b, oc-chunk), smem 128x32 tile
// ---------------------------------------------------------------------------
__global__ void __launch_bounds__(256) finalize_kernel(float* __restrict__ out) {
    int bid = blockIdx.x;
    int occ = bid & 3;
    int b   = (bid >> 2) & 31;
    int y   = (bid >> 7) & 31;
    int d   = bid >> 12;

    __shared__ float sm[128][33];

    for (int i = threadIdx.x; i < 128 * 32; i += 256) {
        int xw = i >> 5;
        int j  = i & 31;
        sm[xw][j] = d_h32[d][y][xw][b][occ * 32 + j];
    }
    __syncthreads();
    for (int i = threadIdx.x; i < 32 * 128; i += 256) {
        int j  = i >> 7;        // channel lane
        int xw = i & 127;       // contiguous writes
        int oc = occ * 32 + j;
        out[(((size_t)(b * 4 + d) * OCC + oc) * HH + y) * WW + xw] = sm[xw][j];
    }
}

// ---------------------------------------------------------------------------
// launch
// ---------------------------------------------------------------------------
extern "C" void kernel_launch(void* const* d_in, const int* in_sizes, int n_in,
                              void* d_out, int out_size) {
    const float* x  = (const float*)d_in[0];
    const float* w0 = (const float*)d_in[1];
    const float* u0 = (const float*)d_in[2];
    const float* u1 = (const float*)d_in[3];
    const float* bb = (const float*)d_in[4];
    float* out = (float*)d_out;
    (void)in_sizes; (void)n_in; (void)out_size;

    cudaFuncSetAttribute(diag_kernel,
                         cudaFuncAttributeMaxDynamicSharedMemorySize, SMEM_BYTES);

    prep_x<<<(HH * WW * BQ * CINC + 255) / 256, 256>>>(x);
    prep_w<<<(NDIR * G5 * KKK + 255) / 256, 256>>>(w0, u0, u1);
    prep_b<<<(NDIR * G5 + 255) / 256, 256>>>(bb);

    for (int t = 0; t < HH + WW - 1; t++) {
        int y0 = t - (WW - 1); if (y0 < 0) y0 = 0;
        int y1 = (t < HH - 1) ? t : (HH - 1);
        int len = y1 - y0 + 1;
        dim3 grid((len + 3) / 4, 4, NDIR);
        diag_kernel<<<grid, 256, SMEM_BYTES>>>(t);
    }

    finalize_kernel<<<NDIR * HH * BQ * 4, 256>>>(out);
}